// round 4
// baseline (speedup 1.0000x reference)
#include <cuda_runtime.h>
#include <cstdint>

#define BB 8
#define LL 2048
#define DD 512
#define DM 128
#define HH 1024        // L/2
#define RR 512         // r_actual = L - K
#define NU 512         // H - RR (unmerged kept)
#define LO 1536        // NU + HH

// ---------------- scratch (static device memory; no runtime allocs) ----------------
__device__ float g_wt[DM * DD];              // W^T  (128 x 512)
__device__ float g_a[BB * HH * DM];          // normalized metric, even tokens
__device__ float g_b[BB * HH * DM];          // normalized metric, odd tokens
__device__ float g_pmax[BB * HH * 2];        // partial row max (2 b-halves)
__device__ int   g_pidx[BB * HH * 2];
__device__ int   g_unm[BB * NU];
__device__ int   g_src[BB * RR];
__device__ int   g_dst[BB * RR];
__device__ int   g_cnt[BB * HH];

// ---------------- W transpose ----------------
__global__ void wt_kernel(const float* __restrict__ W) {
    int idx = blockIdx.x * 256 + threadIdx.x;
    if (idx < DD * DM) {
        int k = idx / DM, c = idx % DM;
        g_wt[c * DD + k] = W[idx];
    }
}

// ---------------- metric = normalize(x @ W) ----------------
// GEMM: ascending-k single-accumulator FMA (bit-matches cublas/Eigen SIMT sgemm).
// Norm: XLA:GPU row-reduction order — warp of 32 "lanes", vec2 loads, 2 x-iters:
//   s_l = ((m[2l]^2 + m[2l+1]^2) + m[2l+64]^2) + m[2l+65]^2
// then shfl.down tree: for off in {16,8,4,2,1}: s_l += s_{l+off}; result = s_0.
#define AST 36    // GEMM smem tile stride (floats)
#define NST 129   // norm staging stride (floats)
__global__ __launch_bounds__(256) void metric_kernel(const float* __restrict__ x) {
    extern __shared__ float dynsm[];        // max(2*128*AST, 128*NST) floats
    __shared__ float norms[128];
    float* xs = dynsm;
    float* ws = dynsm + 128 * AST;

    int tid = threadIdx.x;
    int tx = tid & 15, ty = tid >> 4;
    int rowbase = blockIdx.x * 128;

    float acc[8][8];
#pragma unroll
    for (int i = 0; i < 8; i++)
#pragma unroll
        for (int j = 0; j < 8; j++) acc[i][j] = 0.f;

    const float4* x4 = (const float4*)x;
    const float4* w4 = (const float4*)g_wt;

    for (int kt = 0; kt < 16; kt++) {
        __syncthreads();
#pragma unroll
        for (int p = 0; p < 4; p++) {
            int idx = p * 256 + tid;
            int r = idx >> 3, k4 = idx & 7;
            *(float4*)&xs[r * AST + k4 * 4] = x4[(size_t)(rowbase + r) * (DD / 4) + kt * 8 + k4];
        }
#pragma unroll
        for (int p = 0; p < 4; p++) {
            int idx = p * 256 + tid;
            int c = idx >> 3, k4 = idx & 7;
            *(float4*)&ws[c * AST + k4 * 4] = w4[(size_t)c * (DD / 4) + kt * 8 + k4];
        }
        __syncthreads();
#pragma unroll
        for (int k4 = 0; k4 < 8; k4++) {
            float4 af[8], bf[8];
#pragma unroll
            for (int i = 0; i < 8; i++) af[i] = *(const float4*)&xs[(ty * 8 + i) * AST + k4 * 4];
#pragma unroll
            for (int j = 0; j < 8; j++) bf[j] = *(const float4*)&ws[(tx * 8 + j) * AST + k4 * 4];
#pragma unroll
            for (int i = 0; i < 8; i++)
#pragma unroll
                for (int j = 0; j < 8; j++) {
                    acc[i][j] = fmaf(af[i].x, bf[j].x, acc[i][j]);
                    acc[i][j] = fmaf(af[i].y, bf[j].y, acc[i][j]);
                    acc[i][j] = fmaf(af[i].z, bf[j].z, acc[i][j]);
                    acc[i][j] = fmaf(af[i].w, bf[j].w, acc[i][j]);
                }
        }
    }

    // ---- stage full rows, then XLA-order norm ----
    __syncthreads();
    float* buf = dynsm;   // [128 rows][NST]
#pragma unroll
    for (int i = 0; i < 8; i++)
#pragma unroll
        for (int j = 0; j < 8; j++)
            buf[(ty * 8 + i) * NST + tx * 8 + j] = acc[i][j];
    __syncthreads();

    if (tid < 128) {
        const float* m = &buf[tid * NST];
        float s[32];
#pragma unroll
        for (int l = 0; l < 32; l++) {
            float t0 = __fmul_rn(m[2 * l],      m[2 * l]);
            float t1 = __fmul_rn(m[2 * l + 1],  m[2 * l + 1]);
            float t2 = __fmul_rn(m[2 * l + 64], m[2 * l + 64]);
            float t3 = __fmul_rn(m[2 * l + 65], m[2 * l + 65]);
            s[l] = __fadd_rn(__fadd_rn(__fadd_rn(t0, t1), t2), t3);
        }
#pragma unroll
        for (int off = 16; off >= 1; off >>= 1)
#pragma unroll
            for (int l = 0; l < 16; l++)
                if (l < off) s[l] = __fadd_rn(s[l], s[l + off]);
        norms[tid] = fmaxf(sqrtf(s[0]), 1e-12f);
    }
    __syncthreads();

#pragma unroll
    for (int i = 0; i < 8; i++) {
        int trow = rowbase + ty * 8 + i;
        int b = trow >> 11;          // / L
        int l = trow & (LL - 1);
        float n = norms[ty * 8 + i];
        float* dstbase = ((l & 1) ? g_b : g_a) + ((size_t)b * HH + (l >> 1)) * DM;
        float4 v0, v1;
        v0.x = __fdiv_rn(acc[i][0], n); v0.y = __fdiv_rn(acc[i][1], n);
        v0.z = __fdiv_rn(acc[i][2], n); v0.w = __fdiv_rn(acc[i][3], n);
        v1.x = __fdiv_rn(acc[i][4], n); v1.y = __fdiv_rn(acc[i][5], n);
        v1.z = __fdiv_rn(acc[i][6], n); v1.w = __fdiv_rn(acc[i][7], n);
        *(float4*)&dstbase[tx * 8]     = v0;
        *(float4*)&dstbase[tx * 8 + 4] = v1;
    }
}

// ---------------- scores = a @ b^T with fused row max/argmax ----------------
// grid 128: b(8) x atile(8, 128 rows) x bhalf(2, 512 cols = 4 chunks of 128)
#define BST 132
__global__ __launch_bounds__(256) void scores_kernel(const int* __restrict__ mask) {
    extern __shared__ float sm[];
    float* as = sm;                 // [128][BST]
    float* bs = sm + 128 * BST;     // [128][BST]

    int tid = threadIdx.x;
    int tx = tid & 15, ty = tid >> 4;
    int bb   = blockIdx.x >> 4;
    int tile = (blockIdx.x >> 1) & 7;
    int half = blockIdx.x & 1;
    int rowbase = tile * 128;

    const float4* ga = (const float4*)(g_a + ((size_t)bb * HH + rowbase) * DM);
#pragma unroll
    for (int p = 0; p < 16; p++) {
        int idx = p * 256 + tid;
        int r = idx >> 5, k4 = idx & 31;
        *(float4*)&as[r * BST + k4 * 4] = ga[(size_t)r * 32 + k4];
    }

    float best[8]; int bidx[8];
#pragma unroll
    for (int i = 0; i < 8; i++) { best[i] = -__int_as_float(0x7f800000); bidx[i] = 0; }

    for (int c4 = 0; c4 < 4; c4++) {
        int ch = half * 4 + c4;
        __syncthreads();
        const float4* gb = (const float4*)(g_b + ((size_t)bb * HH + ch * 128) * DM);
#pragma unroll
        for (int p = 0; p < 16; p++) {
            int idx = p * 256 + tid;
            int r = idx >> 5, k4 = idx & 31;
            *(float4*)&bs[r * BST + k4 * 4] = gb[(size_t)r * 32 + k4];
        }
        __syncthreads();

        float acc[8][8];
#pragma unroll
        for (int i = 0; i < 8; i++)
#pragma unroll
            for (int j = 0; j < 8; j++) acc[i][j] = 0.f;

#pragma unroll
        for (int k4 = 0; k4 < 32; k4++) {
            float4 af[8], bf[8];
#pragma unroll
            for (int i = 0; i < 8; i++) af[i] = *(const float4*)&as[(ty * 8 + i) * BST + k4 * 4];
#pragma unroll
            for (int j = 0; j < 8; j++) bf[j] = *(const float4*)&bs[(tx * 8 + j) * BST + k4 * 4];
#pragma unroll
            for (int i = 0; i < 8; i++)
#pragma unroll
                for (int j = 0; j < 8; j++) {
                    acc[i][j] = fmaf(af[i].x, bf[j].x, acc[i][j]);
                    acc[i][j] = fmaf(af[i].y, bf[j].y, acc[i][j]);
                    acc[i][j] = fmaf(af[i].z, bf[j].z, acc[i][j]);
                    acc[i][j] = fmaf(af[i].w, bf[j].w, acc[i][j]);
                }
        }

        bool bm[8];
#pragma unroll
        for (int j = 0; j < 8; j++)
            bm[j] = mask[(size_t)bb * LL + 2 * (ch * 128 + tx * 8 + j) + 1] != 0;

#pragma unroll
        for (int i = 0; i < 8; i++)
#pragma unroll
            for (int j = 0; j < 8; j++) {
                if (bm[j]) {
                    float v = acc[i][j];
                    if (v > best[i]) { best[i] = v; bidx[i] = ch * 128 + tx * 8 + j; }
                }
            }
    }

    // row-mask override (fully masked a-row -> -inf / 0, matching jnp.argmax)
#pragma unroll
    for (int i = 0; i < 8; i++) {
        if (mask[(size_t)bb * LL + 2 * (rowbase + ty * 8 + i)] == 0) {
            best[i] = -__int_as_float(0x7f800000);
            bidx[i] = 0;
        }
    }

    // reduce across tx (16 candidates/row); ties -> lowest column index
    __syncthreads();
    float* rv = as;
    int*   ri = (int*)bs;
#pragma unroll
    for (int i = 0; i < 8; i++) {
        rv[(ty * 8 + i) * 16 + tx] = best[i];
        ri[(ty * 8 + i) * 16 + tx] = bidx[i];
    }
    __syncthreads();
    if (tid < 128) {
        float bv = rv[tid * 16]; int bi = ri[tid * 16];
        for (int t = 1; t < 16; t++) {
            float v = rv[tid * 16 + t]; int ii = ri[tid * 16 + t];
            if (v > bv || (v == bv && ii < bi)) { bv = v; bi = ii; }
        }
        size_t o = ((size_t)bb * HH + rowbase + tid) * 2 + half;
        g_pmax[o] = bv;
        g_pidx[o] = bi;
    }
}

// ---------------- combine halves + stable sort + index build ----------------
__global__ void sort_kernel() {
    __shared__ unsigned long long key[HH];
    __shared__ int nidx[HH];
    int b = blockIdx.x, tid = threadIdx.x;

    for (int t = tid; t < HH; t += 512) {
        size_t o = ((size_t)b * HH + t) * 2;
        float v0 = g_pmax[o], v1 = g_pmax[o + 1];
        int i0 = g_pidx[o], i1 = g_pidx[o + 1];
        float v; int ii;
        if (v1 > v0) { v = v1; ii = i1; } else { v = v0; ii = i0; }  // tie -> lower col (half0)
        nidx[t] = ii;
        unsigned u = __float_as_uint(v);
        u = (u & 0x80000000u) ? ~u : (u | 0x80000000u);   // monotone map
        key[t] = ((unsigned long long)(~u) << 32) | (unsigned)t; // desc val, asc idx (stable)
    }
    __syncthreads();

    for (int k = 2; k <= HH; k <<= 1) {
        for (int j = k >> 1; j > 0; j >>= 1) {
            for (int t = tid; t < HH; t += 512) {
                int ixj = t ^ j;
                if (ixj > t) {
                    bool up = (t & k) == 0;
                    unsigned long long a = key[t], c = key[ixj];
                    if ((a > c) == up) { key[t] = c; key[ixj] = a; }
                }
            }
            __syncthreads();
        }
    }

    for (int p = tid; p < HH; p += 512) {
        int token = (int)(key[p] & 0xFFFFFFFFu);
        if (p < RR) {
            g_src[b * RR + p] = token;
            g_dst[b * RR + p] = nidx[token];
        } else {
            g_unm[b * NU + (p - RR)] = token;
        }
    }
}

// ---------------- assembly ----------------
__global__ void gather_kernel(const float* __restrict__ x, float* __restrict__ out) {
    int bi = blockIdx.x;
    int b = bi / LO, k = bi % LO;
    int srcrow, col1;
    if (k < NU) { int t = g_unm[b * NU + k]; srcrow = 2 * t; col1 = 2 * t; }
    else        { int j = k - NU; srcrow = 2 * j + 1; col1 = srcrow; }

    const float4* src = (const float4*)(x + ((size_t)b * LL + srcrow) * DD);
    float4* dst = (float4*)(out + ((size_t)b * LO + k) * DD);
    dst[threadIdx.x] = src[threadIdx.x];

    if (threadIdx.x == 0) {
        float* osrc = out + (size_t)BB * LO * DD;
        osrc[((size_t)b * LO + k) * LL + col1] = 1.0f;
        if (k >= NU) g_cnt[b * HH + (k - NU)] = 1;
    }
}

__global__ void scatter_kernel(const float* __restrict__ x, float* __restrict__ out) {
    int bi = blockIdx.x;
    int b = bi / RR, k = bi % RR;
    int s = g_src[b * RR + k], dd = g_dst[b * RR + k];
    const float4* src = (const float4*)(x + ((size_t)b * LL + 2 * s) * DD);
    float* dst = out + ((size_t)b * LO + NU + dd) * DD;
    float4 v = src[threadIdx.x];
    int c = threadIdx.x * 4;
    atomicAdd(dst + c,     v.x);
    atomicAdd(dst + c + 1, v.y);
    atomicAdd(dst + c + 2, v.z);
    atomicAdd(dst + c + 3, v.w);
    if (threadIdx.x == 0) {
        atomicAdd(&g_cnt[b * HH + dd], 1);
        float* osrc = out + (size_t)BB * LO * DD;
        osrc[((size_t)b * LO + NU + dd) * LL + 2 * s] = 1.0f;
    }
}

__global__ void div_kernel(float* __restrict__ out) {
    int bi = blockIdx.x;
    int b = bi / HH, j = bi % HH;
    int c = g_cnt[b * HH + j];
    if (c <= 1) return;
    float fc = (float)c;
    float4* row = (float4*)(out + ((size_t)b * LO + NU + j) * DD);
    float4 v = row[threadIdx.x];
    v.x = __fdiv_rn(v.x, fc); v.y = __fdiv_rn(v.y, fc);
    v.z = __fdiv_rn(v.z, fc); v.w = __fdiv_rn(v.w, fc);
    row[threadIdx.x] = v;
}

// ---------------- launch ----------------
extern "C" void kernel_launch(void* const* d_in, const int* in_sizes, int n_in,
                              void* d_out, int out_size) {
    const float* x = (const float*)d_in[0];
    const float* W = (const float*)d_in[1];
    const int* mask = (const int*)d_in[2];
    float* out = (float*)d_out;

    (void)in_sizes; (void)n_in; (void)out_size;

    int metric_smem = 128 * NST * (int)sizeof(float);   // 66048 B (covers GEMM tiles too)
    cudaFuncSetAttribute(metric_kernel, cudaFuncAttributeMaxDynamicSharedMemorySize,
                         metric_smem);
    cudaFuncSetAttribute(scores_kernel, cudaFuncAttributeMaxDynamicSharedMemorySize,
                         2 * 128 * BST * (int)sizeof(float));

    // zero the source matrix region (x_merged region is fully written)
    cudaMemsetAsync(out + (size_t)BB * LO * DD, 0,
                    (size_t)BB * LO * LL * sizeof(float), 0);

    wt_kernel<<<(DD * DM + 255) / 256, 256>>>(W);
    metric_kernel<<<(BB * LL) / 128, 256, metric_smem>>>(x);
    scores_kernel<<<BB * 8 * 2, 256, 2 * 128 * BST * sizeof(float)>>>(mask);
    sort_kernel<<<BB, 512>>>();
    gather_kernel<<<BB * LO, 128>>>(x, out);
    scatter_kernel<<<BB * RR, 128>>>(x, out);
    div_kernel<<<BB * HH, 128>>>(out);
}

// round 5
// speedup vs baseline: 2.3147x; 2.3147x over previous
#include <cuda_runtime.h>
#include <cstdint>

#define BB 8
#define LL 2048
#define DD 512
#define DM 128
#define HH 1024        // L/2
#define RR 512         // r_actual = L - K
#define NU 512         // H - RR (unmerged kept)
#define LO 1536        // NU + HH

// ---------------- packed f32x2 helpers (2 independent IEEE fp32 FMAs / instr) ----------------
__device__ __forceinline__ void fma2(unsigned long long& d, unsigned long long a,
                                     unsigned long long b, unsigned long long c) {
    asm("fma.rn.f32x2 %0, %1, %2, %3;" : "=l"(d) : "l"(a), "l"(b), "l"(c));
}
__device__ __forceinline__ unsigned long long dup2(float a) {
    unsigned long long r;
    asm("mov.b64 %0, {%1, %1};" : "=l"(r) : "f"(a));
    return r;
}
__device__ __forceinline__ void unpack2(float& lo, float& hi, unsigned long long v) {
    asm("mov.b64 {%0, %1}, %2;" : "=f"(lo), "=f"(hi) : "l"(v));
}

// ---------------- scratch (static device memory; no runtime allocs) ----------------
__device__ float g_a[BB * HH * DM];          // normalized metric, even tokens
__device__ float g_b[BB * HH * DM];          // normalized metric, odd tokens
__device__ float g_pmax[BB * HH * 2];        // partial row max (2 b-halves)
__device__ int   g_pidx[BB * HH * 2];
__device__ int   g_unm[BB * NU];
__device__ int   g_src[BB * RR];
__device__ int   g_dst[BB * RR];
__device__ int   g_cnt[BB * HH];

// ---------------- metric = normalize(x @ W) ----------------
// GEMM: ascending-k single-accumulator FMA per output element (bit-matches round 4).
// Norm: XLA warp-reduce order (vec2 loads, 2 x-iters, shfl-down tree) — FROZEN, bit-exact.
// 512 threads: tx = tid&31 owns 4 cols (tx*4..+3), ty = tid>>5 owns 8 rows (ty*8+i).
// x tile: xs[row][k] stride 36 (k-tile 32). W tile: ws[k][col] stride 132 (W is [k][col] global).
#define XST 36
#define WST 132
#define NST 129   // norm staging stride (floats) — identical to round 4
__global__ __launch_bounds__(512) void metric_kernel(const float* __restrict__ x,
                                                     const float* __restrict__ W) {
    extern __shared__ float dynsm[];        // 128*NST floats (covers GEMM tiles)
    __shared__ float norms[128];
    float* xs = dynsm;                       // [128][XST]
    float* ws = dynsm + 128 * XST;           // [32][WST]

    int tid = threadIdx.x;
    int tx = tid & 31, ty = tid >> 5;
    int rowbase = blockIdx.x * 128;

    unsigned long long acc2[8][2];
#pragma unroll
    for (int i = 0; i < 8; i++) { acc2[i][0] = 0ull; acc2[i][1] = 0ull; }

    const float4* x4 = (const float4*)x;
    const float4* w4 = (const float4*)W;

    for (int kt = 0; kt < 16; kt++) {
        __syncthreads();
        // xs: 128 rows x 32 k = 1024 float4, 2 per thread
#pragma unroll
        for (int p = 0; p < 2; p++) {
            int idx = p * 512 + tid;
            int r = idx >> 3, q = idx & 7;
            *(float4*)&xs[r * XST + q * 4] = x4[(size_t)(rowbase + r) * (DD / 4) + kt * 8 + q];
        }
        // ws: 32 k x 128 col = 1024 float4, 2 per thread (W global already [k][col])
#pragma unroll
        for (int p = 0; p < 2; p++) {
            int idx = p * 512 + tid;
            int k = idx >> 5, q = idx & 31;
            *(float4*)&ws[k * WST + q * 4] = w4[(size_t)(kt * 32 + k) * (DM / 4) + q];
        }
        __syncthreads();
#pragma unroll
        for (int k4 = 0; k4 < 8; k4++) {
            float4 af[8];
#pragma unroll
            for (int i = 0; i < 8; i++)
                af[i] = *(const float4*)&xs[(ty * 8 + i) * XST + k4 * 4];
#pragma unroll
            for (int kk = 0; kk < 4; kk++) {
                ulonglong2 b2 = *(const ulonglong2*)&ws[(k4 * 4 + kk) * WST + tx * 4];
#pragma unroll
                for (int i = 0; i < 8; i++) {
                    float a = (kk == 0) ? af[i].x : (kk == 1) ? af[i].y : (kk == 2) ? af[i].z : af[i].w;
                    unsigned long long a2 = dup2(a);
                    fma2(acc2[i][0], a2, b2.x, acc2[i][0]);
                    fma2(acc2[i][1], a2, b2.y, acc2[i][1]);
                }
            }
        }
    }

    // unpack accumulators
    float acc[8][4];
#pragma unroll
    for (int i = 0; i < 8; i++) {
        unpack2(acc[i][0], acc[i][1], acc2[i][0]);
        unpack2(acc[i][2], acc[i][3], acc2[i][1]);
    }

    // ---- stage full rows, then XLA-order norm (identical to round 4) ----
    __syncthreads();
    float* buf = dynsm;   // [128 rows][NST]
#pragma unroll
    for (int i = 0; i < 8; i++)
#pragma unroll
        for (int c = 0; c < 4; c++)
            buf[(ty * 8 + i) * NST + tx * 4 + c] = acc[i][c];
    __syncthreads();

    if (tid < 128) {
        const float* m = &buf[tid * NST];
        float s[32];
#pragma unroll
        for (int l = 0; l < 32; l++) {
            float t0 = __fmul_rn(m[2 * l],      m[2 * l]);
            float t1 = __fmul_rn(m[2 * l + 1],  m[2 * l + 1]);
            float t2 = __fmul_rn(m[2 * l + 64], m[2 * l + 64]);
            float t3 = __fmul_rn(m[2 * l + 65], m[2 * l + 65]);
            s[l] = __fadd_rn(__fadd_rn(__fadd_rn(t0, t1), t2), t3);
        }
#pragma unroll
        for (int off = 16; off >= 1; off >>= 1)
#pragma unroll
            for (int l = 0; l < 16; l++)
                if (l < off) s[l] = __fadd_rn(s[l], s[l + off]);
        norms[tid] = fmaxf(sqrtf(s[0]), 1e-12f);
    }
    __syncthreads();

#pragma unroll
    for (int i = 0; i < 8; i++) {
        int trow = rowbase + ty * 8 + i;
        int b = trow >> 11;          // / L
        int l = trow & (LL - 1);
        float n = norms[ty * 8 + i];
        float* dstbase = ((l & 1) ? g_b : g_a) + ((size_t)b * HH + (l >> 1)) * DM;
        float4 v;
        v.x = __fdiv_rn(acc[i][0], n); v.y = __fdiv_rn(acc[i][1], n);
        v.z = __fdiv_rn(acc[i][2], n); v.w = __fdiv_rn(acc[i][3], n);
        *(float4*)&dstbase[tx * 4] = v;
    }
}

// ---------------- scores = a @ b^T with fused row max/argmax ----------------
// grid 128: b(8) x atile(8, 128 rows) x bhalf(2, 512 cols = 4 chunks of 128)
// 512 threads: tx = tid&31 owns 4 b-cols, ty = tid>>5 owns 8 a-rows.
// as[row][k] stride 132; bs[k][col] stride 132 (transposed on load).
#define AST2 132
#define BST2 132
__global__ __launch_bounds__(512) void scores_kernel(const int* __restrict__ mask) {
    extern __shared__ float sm[];
    float* as = sm;                  // [128][AST2]
    float* bs = sm + 128 * AST2;     // [128][BST2]  (k-major)

    int tid = threadIdx.x;
    int tx = tid & 31, ty = tid >> 5;
    int bb   = blockIdx.x >> 4;
    int tile = (blockIdx.x >> 1) & 7;
    int half = blockIdx.x & 1;
    int rowbase = tile * 128;

    // load a tile [row][k]: 4096 float4, 8 per thread
    const float4* ga = (const float4*)(g_a + ((size_t)bb * HH + rowbase) * DM);
#pragma unroll
    for (int p = 0; p < 8; p++) {
        int idx = p * 512 + tid;
        int r = idx >> 5, q = idx & 31;
        *(float4*)&as[r * AST2 + q * 4] = ga[(size_t)r * 32 + q];
    }

    float best[8]; int bidx[8];
#pragma unroll
    for (int i = 0; i < 8; i++) { best[i] = -__int_as_float(0x7f800000); bidx[i] = 0; }

    for (int c4 = 0; c4 < 4; c4++) {
        int ch = half * 4 + c4;
        __syncthreads();
        // load b chunk transposed -> bs[k][col]
        const float4* gb = (const float4*)(g_b + ((size_t)bb * HH + ch * 128) * DM);
#pragma unroll
        for (int p = 0; p < 8; p++) {
            int idx = p * 512 + tid;
            int tok = idx >> 5, q = idx & 31;   // token (col), feature quad
            float4 v = gb[(size_t)tok * 32 + q];
            bs[(q * 4 + 0) * BST2 + tok] = v.x;
            bs[(q * 4 + 1) * BST2 + tok] = v.y;
            bs[(q * 4 + 2) * BST2 + tok] = v.z;
            bs[(q * 4 + 3) * BST2 + tok] = v.w;
        }
        __syncthreads();

        unsigned long long acc2[8][2];
#pragma unroll
        for (int i = 0; i < 8; i++) { acc2[i][0] = 0ull; acc2[i][1] = 0ull; }

#pragma unroll
        for (int k4 = 0; k4 < 32; k4++) {
            float4 af[8];
#pragma unroll
            for (int i = 0; i < 8; i++)
                af[i] = *(const float4*)&as[(ty * 8 + i) * AST2 + k4 * 4];
#pragma unroll
            for (int kk = 0; kk < 4; kk++) {
                ulonglong2 b2 = *(const ulonglong2*)&bs[(k4 * 4 + kk) * BST2 + tx * 4];
#pragma unroll
                for (int i = 0; i < 8; i++) {
                    float a = (kk == 0) ? af[i].x : (kk == 1) ? af[i].y : (kk == 2) ? af[i].z : af[i].w;
                    unsigned long long a2 = dup2(a);
                    fma2(acc2[i][0], a2, b2.x, acc2[i][0]);
                    fma2(acc2[i][1], a2, b2.y, acc2[i][1]);
                }
            }
        }

        float acc[8][4];
#pragma unroll
        for (int i = 0; i < 8; i++) {
            unpack2(acc[i][0], acc[i][1], acc2[i][0]);
            unpack2(acc[i][2], acc[i][3], acc2[i][1]);
        }

        bool bm[4];
#pragma unroll
        for (int c = 0; c < 4; c++)
            bm[c] = mask[(size_t)bb * LL + 2 * (ch * 128 + tx * 4 + c) + 1] != 0;

#pragma unroll
        for (int i = 0; i < 8; i++)
#pragma unroll
            for (int c = 0; c < 4; c++) {
                if (bm[c]) {
                    float v = acc[i][c];
                    if (v > best[i]) { best[i] = v; bidx[i] = ch * 128 + tx * 4 + c; }
                }
            }
    }

    // row-mask override (fully masked a-row -> -inf / 0, matching jnp.argmax)
#pragma unroll
    for (int i = 0; i < 8; i++) {
        if (mask[(size_t)bb * LL + 2 * (rowbase + ty * 8 + i)] == 0) {
            best[i] = -__int_as_float(0x7f800000);
            bidx[i] = 0;
        }
    }

    // reduce across tx (32 candidates/row); exact ties -> lowest column index
    __syncthreads();
    float* rv = as;          // [128][32]
    int*   ri = (int*)bs;    // [128][32]
#pragma unroll
    for (int i = 0; i < 8; i++) {
        rv[(ty * 8 + i) * 32 + tx] = best[i];
        ri[(ty * 8 + i) * 32 + tx] = bidx[i];
    }
    __syncthreads();
    if (tid < 128) {
        float bv = rv[tid * 32]; int bi = ri[tid * 32];
        for (int t = 1; t < 32; t++) {
            float v = rv[tid * 32 + t]; int ii = ri[tid * 32 + t];
            if (v > bv || (v == bv && ii < bi)) { bv = v; bi = ii; }
        }
        size_t o = ((size_t)bb * HH + rowbase + tid) * 2 + half;
        g_pmax[o] = bv;
        g_pidx[o] = bi;
    }
}

// ---------------- combine halves + stable sort + index build ----------------
__global__ void sort_kernel() {
    __shared__ unsigned long long key[HH];
    __shared__ int nidx[HH];
    int b = blockIdx.x, tid = threadIdx.x;

    for (int t = tid; t < HH; t += 512) {
        size_t o = ((size_t)b * HH + t) * 2;
        float v0 = g_pmax[o], v1 = g_pmax[o + 1];
        int i0 = g_pidx[o], i1 = g_pidx[o + 1];
        float v; int ii;
        if (v1 > v0) { v = v1; ii = i1; } else { v = v0; ii = i0; }  // tie -> lower col (half0)
        nidx[t] = ii;
        unsigned u = __float_as_uint(v);
        u = (u & 0x80000000u) ? ~u : (u | 0x80000000u);   // monotone map
        key[t] = ((unsigned long long)(~u) << 32) | (unsigned)t; // desc val, asc idx (stable)
    }
    __syncthreads();

    for (int k = 2; k <= HH; k <<= 1) {
        for (int j = k >> 1; j > 0; j >>= 1) {
            for (int t = tid; t < HH; t += 512) {
                int ixj = t ^ j;
                if (ixj > t) {
                    bool up = (t & k) == 0;
                    unsigned long long a = key[t], c = key[ixj];
                    if ((a > c) == up) { key[t] = c; key[ixj] = a; }
                }
            }
            __syncthreads();
        }
    }

    for (int p = tid; p < HH; p += 512) {
        int token = (int)(key[p] & 0xFFFFFFFFu);
        if (p < RR) {
            g_src[b * RR + p] = token;
            g_dst[b * RR + p] = nidx[token];
        } else {
            g_unm[b * NU + (p - RR)] = token;
        }
    }
}

// ---------------- assembly ----------------
__global__ void gather_kernel(const float* __restrict__ x, float* __restrict__ out) {
    int bi = blockIdx.x;
    int b = bi / LO, k = bi % LO;
    int srcrow, col1;
    if (k < NU) { int t = g_unm[b * NU + k]; srcrow = 2 * t; col1 = 2 * t; }
    else        { int j = k - NU; srcrow = 2 * j + 1; col1 = srcrow; }

    const float4* src = (const float4*)(x + ((size_t)b * LL + srcrow) * DD);
    float4* dst = (float4*)(out + ((size_t)b * LO + k) * DD);
    dst[threadIdx.x] = src[threadIdx.x];

    if (threadIdx.x == 0) {
        float* osrc = out + (size_t)BB * LO * DD;
        osrc[((size_t)b * LO + k) * LL + col1] = 1.0f;
        if (k >= NU) g_cnt[b * HH + (k - NU)] = 1;
    }
}

__global__ void scatter_kernel(const float* __restrict__ x, float* __restrict__ out) {
    int bi = blockIdx.x;
    int b = bi / RR, k = bi % RR;
    int s = g_src[b * RR + k], dd = g_dst[b * RR + k];
    const float4* src = (const float4*)(x + ((size_t)b * LL + 2 * s) * DD);
    float* dst = out + ((size_t)b * LO + NU + dd) * DD;
    float4 v = src[threadIdx.x];
    int c = threadIdx.x * 4;
    atomicAdd(dst + c,     v.x);
    atomicAdd(dst + c + 1, v.y);
    atomicAdd(dst + c + 2, v.z);
    atomicAdd(dst + c + 3, v.w);
    if (threadIdx.x == 0) {
        atomicAdd(&g_cnt[b * HH + dd], 1);
        float* osrc = out + (size_t)BB * LO * DD;
        osrc[((size_t)b * LO + NU + dd) * LL + 2 * s] = 1.0f;
    }
}

__global__ void div_kernel(float* __restrict__ out) {
    int bi = blockIdx.x;
    int b = bi / HH, j = bi % HH;
    int c = g_cnt[b * HH + j];
    if (c <= 1) return;
    float fc = (float)c;
    float4* row = (float4*)(out + ((size_t)b * LO + NU + j) * DD);
    float4 v = row[threadIdx.x];
    v.x = __fdiv_rn(v.x, fc); v.y = __fdiv_rn(v.y, fc);
    v.z = __fdiv_rn(v.z, fc); v.w = __fdiv_rn(v.w, fc);
    row[threadIdx.x] = v;
}

// ---------------- launch ----------------
extern "C" void kernel_launch(void* const* d_in, const int* in_sizes, int n_in,
                              void* d_out, int out_size) {
    const float* x = (const float*)d_in[0];
    const float* W = (const float*)d_in[1];
    const int* mask = (const int*)d_in[2];
    float* out = (float*)d_out;

    (void)in_sizes; (void)n_in; (void)out_size;

    int metric_smem = 128 * NST * (int)sizeof(float);                 // 66048 B
    int scores_smem = (128 * AST2 + 128 * BST2) * (int)sizeof(float); // 135168 B
    cudaFuncSetAttribute(metric_kernel, cudaFuncAttributeMaxDynamicSharedMemorySize,
                         metric_smem);
    cudaFuncSetAttribute(scores_kernel, cudaFuncAttributeMaxDynamicSharedMemorySize,
                         scores_smem);

    // zero the source matrix region (x_merged region is fully written)
    cudaMemsetAsync(out + (size_t)BB * LO * DD, 0,
                    (size_t)BB * LO * LL * sizeof(float), 0);

    metric_kernel<<<(BB * LL) / 128, 512, metric_smem>>>(x, W);
    scores_kernel<<<BB * 8 * 2, 512, scores_smem>>>(mask);
    sort_kernel<<<BB, 512>>>();
    gather_kernel<<<BB * LO, 128>>>(x, out);
    scatter_kernel<<<BB * RR, 128>>>(x, out);
    div_kernel<<<BB * HH, 128>>>(out);
}

// round 6
// speedup vs baseline: 2.5200x; 1.0887x over previous
#include <cuda_runtime.h>
#include <cstdint>

#define BB 8
#define LL 2048
#define DD 512
#define DM 128
#define HH 1024        // L/2
#define RR 512         // r_actual = L - K
#define NU 512         // H - RR (unmerged kept)
#define LO 1536        // NU + HH

// ---------------- packed f32x2 helpers (2 independent IEEE fp32 FMAs / instr) ----------------
__device__ __forceinline__ void fma2(unsigned long long& d, unsigned long long a,
                                     unsigned long long b, unsigned long long c) {
    asm("fma.rn.f32x2 %0, %1, %2, %3;" : "=l"(d) : "l"(a), "l"(b), "l"(c));
}
__device__ __forceinline__ unsigned long long dup2(float a) {
    unsigned long long r;
    asm("mov.b64 %0, {%1, %1};" : "=l"(r) : "f"(a));
    return r;
}
__device__ __forceinline__ void unpack2(float& lo, float& hi, unsigned long long v) {
    asm("mov.b64 {%0, %1}, %2;" : "=f"(lo), "=f"(hi) : "l"(v));
}

// ---------------- scratch (static device memory; no runtime allocs) ----------------
__device__ float g_a[BB * HH * DM];          // normalized metric, even tokens
__device__ float g_b[BB * HH * DM];          // normalized metric, odd tokens
__device__ float g_pmax[BB * HH * 2];        // partial row max (2 b-halves)
__device__ int   g_pidx[BB * HH * 2];
__device__ int   g_unm[BB * NU];
__device__ int   g_src[BB * RR];
__device__ int   g_dst[BB * RR];
__device__ int   g_cnt[BB * HH];

// ---------------- metric = normalize(x @ W) ----------------
// GEMM: ascending-k single-accumulator FMA per output element — FROZEN numerics.
// Norm: XLA warp-reduce order (vec2 loads, 2 x-iters, shfl-down tree) — FROZEN.
#define XST 36
#define WST 132
#define NST 129
__global__ __launch_bounds__(512) void metric_kernel(const float* __restrict__ x,
                                                     const float* __restrict__ W) {
    extern __shared__ float dynsm[];        // 128*NST floats (covers GEMM tiles)
    __shared__ float norms[128];
    float* xs = dynsm;                       // [128][XST]
    float* ws = dynsm + 128 * XST;           // [32][WST]

    int tid = threadIdx.x;
    int tx = tid & 31, ty = tid >> 5;
    int rowbase = blockIdx.x * 128;

    unsigned long long acc2[8][2];
#pragma unroll
    for (int i = 0; i < 8; i++) { acc2[i][0] = 0ull; acc2[i][1] = 0ull; }

    const float4* x4 = (const float4*)x;
    const float4* w4 = (const float4*)W;

    for (int kt = 0; kt < 16; kt++) {
        __syncthreads();
#pragma unroll
        for (int p = 0; p < 2; p++) {
            int idx = p * 512 + tid;
            int r = idx >> 3, q = idx & 7;
            *(float4*)&xs[r * XST + q * 4] = x4[(size_t)(rowbase + r) * (DD / 4) + kt * 8 + q];
        }
#pragma unroll
        for (int p = 0; p < 2; p++) {
            int idx = p * 512 + tid;
            int k = idx >> 5, q = idx & 31;
            *(float4*)&ws[k * WST + q * 4] = w4[(size_t)(kt * 32 + k) * (DM / 4) + q];
        }
        __syncthreads();
#pragma unroll
        for (int k4 = 0; k4 < 8; k4++) {
            float4 af[8];
#pragma unroll
            for (int i = 0; i < 8; i++)
                af[i] = *(const float4*)&xs[(ty * 8 + i) * XST + k4 * 4];
#pragma unroll
            for (int kk = 0; kk < 4; kk++) {
                ulonglong2 b2 = *(const ulonglong2*)&ws[(k4 * 4 + kk) * WST + tx * 4];
#pragma unroll
                for (int i = 0; i < 8; i++) {
                    float a = (kk == 0) ? af[i].x : (kk == 1) ? af[i].y : (kk == 2) ? af[i].z : af[i].w;
                    unsigned long long a2 = dup2(a);
                    fma2(acc2[i][0], a2, b2.x, acc2[i][0]);
                    fma2(acc2[i][1], a2, b2.y, acc2[i][1]);
                }
            }
        }
    }

    float acc[8][4];
#pragma unroll
    for (int i = 0; i < 8; i++) {
        unpack2(acc[i][0], acc[i][1], acc2[i][0]);
        unpack2(acc[i][2], acc[i][3], acc2[i][1]);
    }

    __syncthreads();
    float* buf = dynsm;   // [128 rows][NST]
#pragma unroll
    for (int i = 0; i < 8; i++)
#pragma unroll
        for (int c = 0; c < 4; c++)
            buf[(ty * 8 + i) * NST + tx * 4 + c] = acc[i][c];
    __syncthreads();

    if (tid < 128) {
        const float* m = &buf[tid * NST];
        float s[32];
#pragma unroll
        for (int l = 0; l < 32; l++) {
            float t0 = __fmul_rn(m[2 * l],      m[2 * l]);
            float t1 = __fmul_rn(m[2 * l + 1],  m[2 * l + 1]);
            float t2 = __fmul_rn(m[2 * l + 64], m[2 * l + 64]);
            float t3 = __fmul_rn(m[2 * l + 65], m[2 * l + 65]);
            s[l] = __fadd_rn(__fadd_rn(__fadd_rn(t0, t1), t2), t3);
        }
#pragma unroll
        for (int off = 16; off >= 1; off >>= 1)
#pragma unroll
            for (int l = 0; l < 16; l++)
                if (l < off) s[l] = __fadd_rn(s[l], s[l + off]);
        norms[tid] = fmaxf(sqrtf(s[0]), 1e-12f);
    }
    __syncthreads();

#pragma unroll
    for (int i = 0; i < 8; i++) {
        int trow = rowbase + ty * 8 + i;
        int b = trow >> 11;
        int l = trow & (LL - 1);
        float n = norms[ty * 8 + i];
        float* dstbase = ((l & 1) ? g_b : g_a) + ((size_t)b * HH + (l >> 1)) * DM;
        float4 v;
        v.x = __fdiv_rn(acc[i][0], n); v.y = __fdiv_rn(acc[i][1], n);
        v.z = __fdiv_rn(acc[i][2], n); v.w = __fdiv_rn(acc[i][3], n);
        *(float4*)&dstbase[tx * 4] = v;
    }
}

// ---------------- scores = a @ b^T with fused row max/argmax ----------------
#define AST2 132
#define BST2 132
__global__ __launch_bounds__(512) void scores_kernel(const int* __restrict__ mask) {
    extern __shared__ float sm[];
    float* as = sm;                  // [128][AST2]
    float* bs = sm + 128 * AST2;     // [128][BST2]  (k-major)

    int tid = threadIdx.x;
    int tx = tid & 31, ty = tid >> 5;
    int bb   = blockIdx.x >> 4;
    int tile = (blockIdx.x >> 1) & 7;
    int half = blockIdx.x & 1;
    int rowbase = tile * 128;

    const float4* ga = (const float4*)(g_a + ((size_t)bb * HH + rowbase) * DM);
#pragma unroll
    for (int p = 0; p < 8; p++) {
        int idx = p * 512 + tid;
        int r = idx >> 5, q = idx & 31;
        *(float4*)&as[r * AST2 + q * 4] = ga[(size_t)r * 32 + q];
    }

    float best[8]; int bidx[8];
#pragma unroll
    for (int i = 0; i < 8; i++) { best[i] = -__int_as_float(0x7f800000); bidx[i] = 0; }

    for (int c4 = 0; c4 < 4; c4++) {
        int ch = half * 4 + c4;
        __syncthreads();
        const float4* gb = (const float4*)(g_b + ((size_t)bb * HH + ch * 128) * DM);
#pragma unroll
        for (int p = 0; p < 8; p++) {
            int idx = p * 512 + tid;
            int tok = idx >> 5, q = idx & 31;
            float4 v = gb[(size_t)tok * 32 + q];
            bs[(q * 4 + 0) * BST2 + tok] = v.x;
            bs[(q * 4 + 1) * BST2 + tok] = v.y;
            bs[(q * 4 + 2) * BST2 + tok] = v.z;
            bs[(q * 4 + 3) * BST2 + tok] = v.w;
        }
        __syncthreads();

        unsigned long long acc2[8][2];
#pragma unroll
        for (int i = 0; i < 8; i++) { acc2[i][0] = 0ull; acc2[i][1] = 0ull; }

#pragma unroll
        for (int k4 = 0; k4 < 32; k4++) {
            float4 af[8];
#pragma unroll
            for (int i = 0; i < 8; i++)
                af[i] = *(const float4*)&as[(ty * 8 + i) * AST2 + k4 * 4];
#pragma unroll
            for (int kk = 0; kk < 4; kk++) {
                ulonglong2 b2 = *(const ulonglong2*)&bs[(k4 * 4 + kk) * BST2 + tx * 4];
#pragma unroll
                for (int i = 0; i < 8; i++) {
                    float a = (kk == 0) ? af[i].x : (kk == 1) ? af[i].y : (kk == 2) ? af[i].z : af[i].w;
                    unsigned long long a2 = dup2(a);
                    fma2(acc2[i][0], a2, b2.x, acc2[i][0]);
                    fma2(acc2[i][1], a2, b2.y, acc2[i][1]);
                }
            }
        }

        float acc[8][4];
#pragma unroll
        for (int i = 0; i < 8; i++) {
            unpack2(acc[i][0], acc[i][1], acc2[i][0]);
            unpack2(acc[i][2], acc[i][3], acc2[i][1]);
        }

        bool bm[4];
#pragma unroll
        for (int c = 0; c < 4; c++)
            bm[c] = mask[(size_t)bb * LL + 2 * (ch * 128 + tx * 4 + c) + 1] != 0;

#pragma unroll
        for (int i = 0; i < 8; i++)
#pragma unroll
            for (int c = 0; c < 4; c++) {
                if (bm[c]) {
                    float v = acc[i][c];
                    if (v > best[i]) { best[i] = v; bidx[i] = ch * 128 + tx * 4 + c; }
                }
            }
    }

#pragma unroll
    for (int i = 0; i < 8; i++) {
        if (mask[(size_t)bb * LL + 2 * (rowbase + ty * 8 + i)] == 0) {
            best[i] = -__int_as_float(0x7f800000);
            bidx[i] = 0;
        }
    }

    __syncthreads();
    float* rv = as;
    int*   ri = (int*)bs;
#pragma unroll
    for (int i = 0; i < 8; i++) {
        rv[(ty * 8 + i) * 32 + tx] = best[i];
        ri[(ty * 8 + i) * 32 + tx] = bidx[i];
    }
    __syncthreads();
    if (tid < 128) {
        float bv = rv[tid * 32]; int bi = ri[tid * 32];
        for (int t = 1; t < 32; t++) {
            float v = rv[tid * 32 + t]; int ii = ri[tid * 32 + t];
            if (v > bv || (v == bv && ii < bi)) { bv = v; bi = ii; }
        }
        size_t o = ((size_t)bb * HH + rowbase + tid) * 2 + half;
        g_pmax[o] = bv;
        g_pidx[o] = bi;
    }
}

// ---------------- combine halves + register bitonic sort + index build ----------------
// 2 keys/thread in registers; j<=32 passes via shfl.xor, j>=64 via smem. Result identical
// to the round-4/5 smem bitonic (same compare network, same keys).
__device__ __forceinline__ unsigned long long cmpx(unsigned long long a,
                                                   unsigned long long p, bool takeMin) {
    return takeMin ? (a < p ? a : p) : (a > p ? a : p);
}
__global__ __launch_bounds__(512) void sort_kernel() {
    __shared__ unsigned long long sk[HH];
    __shared__ int nidx[HH];
    int b = blockIdx.x, tid = threadIdx.x;
    int e0 = 2 * tid, e1 = 2 * tid + 1;

    unsigned long long k0, k1;
#pragma unroll
    for (int c = 0; c < 2; c++) {
        int t = e0 + c;
        size_t o = ((size_t)b * HH + t) * 2;
        float v0 = g_pmax[o], v1 = g_pmax[o + 1];
        int i0 = g_pidx[o], i1 = g_pidx[o + 1];
        float v; int ii;
        if (v1 > v0) { v = v1; ii = i1; } else { v = v0; ii = i0; }
        nidx[t] = ii;
        unsigned u = __float_as_uint(v);
        u = (u & 0x80000000u) ? ~u : (u | 0x80000000u);
        unsigned long long key = ((unsigned long long)(~u) << 32) | (unsigned)t;
        if (c == 0) k0 = key; else k1 = key;
    }
    __syncthreads();   // nidx published

    for (int k = 2; k <= HH; k <<= 1) {
        bool up = ((e0 & k) == 0);
        for (int j = k >> 1; j >= 64; j >>= 1) {
            sk[e0] = k0; sk[e1] = k1;
            __syncthreads();
            unsigned long long p0 = sk[e0 ^ j], p1 = sk[e1 ^ j];
            bool takeMin = (up == ((e0 & j) == 0));
            k0 = cmpx(k0, p0, takeMin);
            k1 = cmpx(k1, p1, takeMin);
            __syncthreads();
        }
        int jstart = ((k >> 1) < 32) ? (k >> 1) : 32;
        for (int j = jstart; j >= 2; j >>= 1) {
            unsigned long long p0 = __shfl_xor_sync(0xffffffffu, k0, j >> 1);
            unsigned long long p1 = __shfl_xor_sync(0xffffffffu, k1, j >> 1);
            bool takeMin = (up == ((e0 & j) == 0));
            k0 = cmpx(k0, p0, takeMin);
            k1 = cmpx(k1, p1, takeMin);
        }
        {   // j == 1: partner is in-thread
            unsigned long long lo = k0 < k1 ? k0 : k1;
            unsigned long long hi = k0 < k1 ? k1 : k0;
            k0 = up ? lo : hi;
            k1 = up ? hi : lo;
        }
    }

#pragma unroll
    for (int c = 0; c < 2; c++) {
        int p = e0 + c;
        unsigned long long key = (c == 0) ? k0 : k1;
        int token = (int)(key & 0xFFFFFFFFu);
        if (p < RR) {
            g_src[b * RR + p] = token;
            g_dst[b * RR + p] = nidx[token];
        } else {
            g_unm[b * NU + (p - RR)] = token;
        }
    }
}

// ---------------- assembly: warp-per-row kernels ----------------
__global__ __launch_bounds__(256) void gather_kernel(const float* __restrict__ x,
                                                     float* __restrict__ out) {
    int w = (blockIdx.x * 256 + threadIdx.x) >> 5;   // 0..12287
    int lane = threadIdx.x & 31;
    int b = w / LO, k = w % LO;
    int srcrow, col1;
    if (k < NU) { int t = g_unm[b * NU + k]; srcrow = 2 * t; col1 = 2 * t; }
    else        { int j = k - NU; srcrow = 2 * j + 1; col1 = srcrow; }

    const float4* src = (const float4*)(x + ((size_t)b * LL + srcrow) * DD);
    float4* dst = (float4*)(out + ((size_t)b * LO + k) * DD);
#pragma unroll
    for (int p = 0; p < 4; p++) dst[lane + 32 * p] = src[lane + 32 * p];

    if (lane == 0) {
        float* osrc = out + (size_t)BB * LO * DD;
        osrc[((size_t)b * LO + k) * LL + col1] = 1.0f;
        if (k >= NU) g_cnt[b * HH + (k - NU)] = 1;
    }
}

__global__ __launch_bounds__(256) void scatter_kernel(const float* __restrict__ x,
                                                      float* __restrict__ out) {
    int w = (blockIdx.x * 256 + threadIdx.x) >> 5;   // 0..4095
    int lane = threadIdx.x & 31;
    int b = w / RR, k = w % RR;
    int s = g_src[b * RR + k], dd = g_dst[b * RR + k];
    const float4* src = (const float4*)(x + ((size_t)b * LL + 2 * s) * DD);
    float* dst = out + ((size_t)b * LO + NU + dd) * DD;
#pragma unroll
    for (int p = 0; p < 4; p++) {
        float4 v = src[lane + 32 * p];
        int c = (lane + 32 * p) * 4;
        atomicAdd(dst + c,     v.x);
        atomicAdd(dst + c + 1, v.y);
        atomicAdd(dst + c + 2, v.z);
        atomicAdd(dst + c + 3, v.w);
    }
    if (lane == 0) {
        atomicAdd(&g_cnt[b * HH + dd], 1);
        float* osrc = out + (size_t)BB * LO * DD;
        osrc[((size_t)b * LO + NU + dd) * LL + 2 * s] = 1.0f;
    }
}

__global__ __launch_bounds__(256) void div_kernel(float* __restrict__ out) {
    int w = (blockIdx.x * 256 + threadIdx.x) >> 5;   // 0..8191
    int lane = threadIdx.x & 31;
    int b = w / HH, j = w % HH;
    int c = g_cnt[b * HH + j];
    if (c <= 1) return;
    float fc = (float)c;
    float4* row = (float4*)(out + ((size_t)b * LO + NU + j) * DD);
#pragma unroll
    for (int p = 0; p < 4; p++) {
        float4 v = row[lane + 32 * p];
        v.x = __fdiv_rn(v.x, fc); v.y = __fdiv_rn(v.y, fc);
        v.z = __fdiv_rn(v.z, fc); v.w = __fdiv_rn(v.w, fc);
        row[lane + 32 * p] = v;
    }
}

// ---------------- launch ----------------
extern "C" void kernel_launch(void* const* d_in, const int* in_sizes, int n_in,
                              void* d_out, int out_size) {
    const float* x = (const float*)d_in[0];
    const float* W = (const float*)d_in[1];
    const int* mask = (const int*)d_in[2];
    float* out = (float*)d_out;

    (void)in_sizes; (void)n_in; (void)out_size;

    // one-time resources (created on the pre-capture correctness call; no device memory)
    static cudaStream_t s2 = nullptr;
    static cudaEvent_t evFork = nullptr, evJoin = nullptr;
    static bool attrs_set = false;
    if (!s2) {
        cudaStreamCreateWithFlags(&s2, cudaStreamNonBlocking);
        cudaEventCreateWithFlags(&evFork, cudaEventDisableTiming);
        cudaEventCreateWithFlags(&evJoin, cudaEventDisableTiming);
    }
    int metric_smem = 128 * NST * (int)sizeof(float);                 // 66048 B
    int scores_smem = (128 * AST2 + 128 * BST2) * (int)sizeof(float); // 135168 B
    if (!attrs_set) {
        cudaFuncSetAttribute(metric_kernel, cudaFuncAttributeMaxDynamicSharedMemorySize,
                             metric_smem);
        cudaFuncSetAttribute(scores_kernel, cudaFuncAttributeMaxDynamicSharedMemorySize,
                             scores_smem);
        attrs_set = true;
    }

    // fork: zero the 100MB source region on s2, overlapped with the FMA-bound GEMMs
    cudaEventRecord(evFork, 0);
    cudaStreamWaitEvent(s2, evFork, 0);
    cudaMemsetAsync(out + (size_t)BB * LO * DD, 0,
                    (size_t)BB * LO * LL * sizeof(float), s2);
    cudaEventRecord(evJoin, s2);

    metric_kernel<<<(BB * LL) / 128, 512, metric_smem>>>(x, W);
    scores_kernel<<<BB * 8 * 2, 512, scores_smem>>>(mask);
    sort_kernel<<<BB, 512>>>();

    // join: assembly needs the zeroed source region
    cudaStreamWaitEvent(0, evJoin, 0);
    gather_kernel<<<BB * LO / 8, 256>>>(x, out);
    scatter_kernel<<<BB * RR / 8, 256>>>(x, out);
    div_kernel<<<BB * HH / 8, 256>>>(out);
}